// round 6
// baseline (speedup 1.0000x reference)
#include <cuda_runtime.h>
#include <math_constants.h>

// Problem constants (from reference setup_inputs)
#define N_IMG 2
#define C_CH  256
#define H_F   64
#define W_F   64
#define HW    (H_F * W_F)
#define R_ROI 128
#define PH    7
#define PW    7
#define NBINS (PH * PW)   // 49
#define SCALE 0.0625f
#define C4    (C_CH / 4)  // 64 float4 per pixel
#define ROWSTRIDE4 (W_F * C4)  // 4096 float4 per feature row

// NHWC scratch: [b][h][w][c], 8 MB
__device__ float TFEAT[N_IMG * HW * C_CH];

// ---------------------------------------------------------------------------
// Kernel 1: NCHW -> NHWC transpose, float4 on both global sides.
// ---------------------------------------------------------------------------
__global__ __launch_bounds__(256) void transpose_kernel(const float* __restrict__ feat)
{
    __shared__ float tile[32][33];   // [c_local][hw_local]
    int b   = blockIdx.z;
    int hw0 = blockIdx.x * 32;
    int c0  = blockIdx.y * 32;
    int tx  = threadIdx.x;   // 0..7
    int ty  = threadIdx.y;   // 0..31

    const float4* src4 = (const float4*)(feat + (size_t)b * C_CH * HW);
    float4*       dst4 = (float4*)(TFEAT + (size_t)b * HW * C_CH);

    float4 v = src4[(size_t)(c0 + ty) * (HW / 4) + (hw0 / 4) + tx];
    tile[ty][4 * tx + 0] = v.x;
    tile[ty][4 * tx + 1] = v.y;
    tile[ty][4 * tx + 2] = v.z;
    tile[ty][4 * tx + 3] = v.w;
    __syncthreads();

    float4 o;
    o.x = tile[4 * tx + 0][ty];
    o.y = tile[4 * tx + 1][ty];
    o.z = tile[4 * tx + 2][ty];
    o.w = tile[4 * tx + 3][ty];
    dst4[(size_t)(hw0 + ty) * C4 + (c0 / 4) + tx] = o;
}

// ---------------------------------------------------------------------------
// Kernel 2: pool + fused output writeback.
// Block = (r, half, bin-group of 7 sharing one ph row). 7 warps, warp = bin.
// __launch_bounds__(224, 6): cap 48 regs -> 6 blocks/SM = 42 warps (66% occ),
// up from reg-limited 39.7% in round 5.
// Bin-bound arithmetic verbatim from the bit-exact kernel.
// ---------------------------------------------------------------------------
__global__ __launch_bounds__(224, 6) void pool_kernel(const float* __restrict__ rois,
                                                      float* __restrict__ out)
{
    __shared__ float sh[PH * 132];   // [bin_local][c_local]

    int blk  = blockIdx.x;           // r*14 + half*7 + g
    int g    = blk % 7;
    int half = (blk / 7) & 1;
    int r    = blk / 14;
    int tid  = threadIdx.x;
    int warp = tid >> 5;             // 0..6 = bin_local
    int lane = tid & 31;
    int bin  = g * 7 + warp;         // 0..48
    int ph   = bin / PW;
    int pw   = bin - ph * PW;

    const float* roi = rois + r * 5;
    int b  = (int)roi[0];
    int sw = (int)rintf(roi[1] * SCALE);
    int sh_ = (int)rintf(roi[2] * SCALE);
    int ew = (int)rintf(roi[3] * SCALE);
    int eh = (int)rintf(roi[4] * SCALE);

    float roi_w = (float)max(ew - sw + 1, 1);
    float roi_h = (float)max(eh - sh_ + 1, 1);
    float bin_h = roi_h * (1.0f / PH);   // bit-exact vs reference
    float bin_w = roi_w * (1.0f / PW);

    int hstart = min(max((int)floorf((float)ph * bin_h) + sh_, 0), H_F);
    int hend   = min(max((int)ceilf(((float)ph + 1.0f) * bin_h) + sh_, 0), H_F);
    int wstart = min(max((int)floorf((float)pw * bin_w) + sw, 0), W_F);
    int wend   = min(max((int)ceilf(((float)pw + 1.0f) * bin_w) + sw, 0), W_F);

    float4 ma, mb;
    if ((hend <= hstart) || (wend <= wstart)) {
        ma = make_float4(0.f, 0.f, 0.f, 0.f);
        mb = ma;
    } else {
        ma = make_float4(-CUDART_INF_F, -CUDART_INF_F, -CUDART_INF_F, -CUDART_INF_F);
        mb = ma;
        const float4* base = (const float4*)TFEAT
                           + (size_t)b * HW * C4 + half * 32 + lane;
        int h = hstart;
        for (; h + 1 < hend; h += 2) {
            const float4* r0 = base + (size_t)h * ROWSTRIDE4;
            const float4* r1 = r0 + ROWSTRIDE4;
            int w = wstart;
            for (; w + 1 < wend; w += 2) {
                float4 a0 = __ldg(r0 + (size_t)w * C4);
                float4 a1 = __ldg(r0 + (size_t)(w + 1) * C4);
                float4 b0 = __ldg(r1 + (size_t)w * C4);
                float4 b1 = __ldg(r1 + (size_t)(w + 1) * C4);
                ma.x = fmaxf(ma.x, fmaxf(a0.x, a1.x));
                ma.y = fmaxf(ma.y, fmaxf(a0.y, a1.y));
                ma.z = fmaxf(ma.z, fmaxf(a0.z, a1.z));
                ma.w = fmaxf(ma.w, fmaxf(a0.w, a1.w));
                mb.x = fmaxf(mb.x, fmaxf(b0.x, b1.x));
                mb.y = fmaxf(mb.y, fmaxf(b0.y, b1.y));
                mb.z = fmaxf(mb.z, fmaxf(b0.z, b1.z));
                mb.w = fmaxf(mb.w, fmaxf(b0.w, b1.w));
            }
            if (w < wend) {
                float4 a0 = __ldg(r0 + (size_t)w * C4);
                float4 b0 = __ldg(r1 + (size_t)w * C4);
                ma.x = fmaxf(ma.x, a0.x); ma.y = fmaxf(ma.y, a0.y);
                ma.z = fmaxf(ma.z, a0.z); ma.w = fmaxf(ma.w, a0.w);
                mb.x = fmaxf(mb.x, b0.x); mb.y = fmaxf(mb.y, b0.y);
                mb.z = fmaxf(mb.z, b0.z); mb.w = fmaxf(mb.w, b0.w);
            }
        }
        if (h < hend) {
            const float4* r0 = base + (size_t)h * ROWSTRIDE4;
            int w = wstart;
            for (; w + 1 < wend; w += 2) {
                float4 a0 = __ldg(r0 + (size_t)w * C4);
                float4 a1 = __ldg(r0 + (size_t)(w + 1) * C4);
                ma.x = fmaxf(ma.x, a0.x); ma.y = fmaxf(ma.y, a0.y);
                ma.z = fmaxf(ma.z, a0.z); ma.w = fmaxf(ma.w, a0.w);
                mb.x = fmaxf(mb.x, a1.x); mb.y = fmaxf(mb.y, a1.y);
                mb.z = fmaxf(mb.z, a1.z); mb.w = fmaxf(mb.w, a1.w);
            }
            if (w < wend) {
                float4 a0 = __ldg(r0 + (size_t)w * C4);
                ma.x = fmaxf(ma.x, a0.x); ma.y = fmaxf(ma.y, a0.y);
                ma.z = fmaxf(ma.z, a0.z); ma.w = fmaxf(ma.w, a0.w);
            }
        }
        ma.x = fmaxf(ma.x, mb.x); ma.y = fmaxf(ma.y, mb.y);
        ma.z = fmaxf(ma.z, mb.z); ma.w = fmaxf(ma.w, mb.w);
    }

    *(float4*)&sh[warp * 132 + lane * 4] = ma;
    __syncthreads();

    // writeback: j = c*7 + binl; stride 224 = 32*7 -> binl invariant, c += 32.
    // out[r][half*128 + c][g*7 + binl]
    float* dst = out + (size_t)r * C_CH * NBINS + (size_t)half * 128 * NBINS + g * 7;
    int c0   = tid / 7;          // 0..31
    int binl = tid - c0 * 7;     // 0..6
    #pragma unroll
    for (int it = 0; it < 4; ++it) {
        int c = c0 + it * 32;
        dst[(size_t)c * NBINS + binl] = sh[binl * 132 + c];
    }
    __syncthreads();
}

extern "C" void kernel_launch(void* const* d_in, const int* in_sizes, int n_in,
                              void* d_out, int out_size)
{
    const float* feat = (const float*)d_in[0];
    const float* rois = (const float*)d_in[1];
    float* out = (float*)d_out;

    dim3 tgrid(HW / 32, C_CH / 32, N_IMG);
    dim3 tblock(8, 32);
    transpose_kernel<<<tgrid, tblock>>>(feat);

    pool_kernel<<<R_ROI * 2 * 7, 224>>>(rois, out);
}